// round 16
// baseline (speedup 1.0000x reference)
#include <cuda_runtime.h>
#include <cuda_bf16.h>

// GGMLLinear: out[o] = sum_k x[k] * scales[o, k/32] * q[o,k] + bias[o]
// x: [1, 4096] f32, q: [14336, 4096] int32 (int8-range), scales: [14336, 128] f32,
// bias: [14336] f32, out: [1, 14336] f32.
//
// Memory-bound GEMV (235MB q stream). R15: persistent CTAs with WARP-
// AUTONOMOUS work stealing. R14 showed persistence works but lost ~4% DRAM to
// the per-tile __syncthreads (MLP drain) and ~1us to the reset kernel. Here:
// each warp independently grabs 2-row units (7168) via one atomicAdd (lane 0
// + shfl broadcast, next grab issued before processing -> ATOMG latency
// hidden), NO barrier in the work loop, and the counter self-resets (last of
// 1036 CTAs zeroes it) so a single kernel is graph-captured. x staged once
// per CTA; mainloop identical to R8 (2 rows/warp, unroll 4, strided-scale
// shuffle, 72-reg cap).

#define IN_DIM 4096
#define OUT_DIM 14336
#define NB (IN_DIM / 32)          // 128 scale blocks per row
#define NUNITS (OUT_DIM / 2)      // 7168 two-row work units
#define THREADS 128
#define GRID (148 * 7)            // one persistent wave, 7 CTAs/SM

__device__ unsigned int g_ctr;    // zero-initialized at module load
__device__ unsigned int g_done;

__global__ __launch_bounds__(THREADS, 7)
void ggml_q8_gemv(const float* __restrict__ x,
                  const int* __restrict__ q,
                  const float* __restrict__ scales,
                  const float* __restrict__ bias,
                  float* __restrict__ out)
{
    __shared__ float xs[IN_DIM];

    // Stage x (16KB) into shared once per CTA.
    {
        const float4* x4 = reinterpret_cast<const float4*>(x);
        float4* xs4 = reinterpret_cast<float4*>(xs);
        #pragma unroll
        for (int i = threadIdx.x; i < IN_DIM / 4; i += THREADS)
            xs4[i] = x4[i];
    }
    __syncthreads();

    const int lane = threadIdx.x & 31;
    const float4* xs4 = reinterpret_cast<const float4*>(xs);
    const int csel = lane >> 3;

    // First grab (per warp).
    unsigned int t;
    if (lane == 0) t = atomicAdd(&g_ctr, 1u);
    t = __shfl_sync(0xffffffffu, t, 0);

    while (t < NUNITS) {
        // Grab the NEXT unit immediately; latency hides under this unit.
        unsigned int nt;
        if (lane == 0) nt = atomicAdd(&g_ctr, 1u);
        nt = __shfl_sync(0xffffffffu, nt, 0);

        const int rowA = (int)(t * 2u);
        const int rowB = rowA + 1;

        const int4* qrowA = reinterpret_cast<const int4*>(q + (size_t)rowA * IN_DIM);
        const int4* qrowB = reinterpret_cast<const int4*>(q + (size_t)rowB * IN_DIM);

        // Preload all 128 scales per row, strided: lane L holds scale[L+32*r].
        // Scale for iter it, lane L: scale[4*it + (L>>3)]
        //   = reg (it>>3) of lane ((it&7)*4 + (L>>3)).
        const float* srowA = scales + (size_t)rowA * NB;
        const float* srowB = scales + (size_t)rowB * NB;
        const float a0 = __ldg(&srowA[lane]);
        const float a1 = __ldg(&srowA[lane + 32]);
        const float a2 = __ldg(&srowA[lane + 64]);
        const float a3 = __ldg(&srowA[lane + 96]);
        const float b0 = __ldg(&srowB[lane]);
        const float b1 = __ldg(&srowB[lane + 32]);
        const float b2 = __ldg(&srowB[lane + 64]);
        const float b3 = __ldg(&srowB[lane + 96]);

        float accA = 0.0f;
        float accB = 0.0f;

        // 1024 int4 per row / 32 lanes = 32 steps. idx4 = it*32 + lane.
        #pragma unroll 4
        for (int it = 0; it < 32; ++it) {
            const int idx4 = it * 32 + lane;
            const int4   qa = __ldg(&qrowA[idx4]);
            const int4   qb = __ldg(&qrowB[idx4]);
            const float4 xv = xs4[idx4];
            const int    src = ((it & 7) << 2) + csel;
            const float  sva = (it < 8) ? a0 : (it < 16) ? a1 : (it < 24) ? a2 : a3;
            const float  svb = (it < 8) ? b0 : (it < 16) ? b1 : (it < 24) ? b2 : b3;
            const float  sA = __shfl_sync(0xffffffffu, sva, src);
            const float  sB = __shfl_sync(0xffffffffu, svb, src);

            float dA = xv.x * (float)qa.x;
            dA = fmaf(xv.y, (float)qa.y, dA);
            dA = fmaf(xv.z, (float)qa.z, dA);
            dA = fmaf(xv.w, (float)qa.w, dA);
            accA = fmaf(sA, dA, accA);

            float dB = xv.x * (float)qb.x;
            dB = fmaf(xv.y, (float)qb.y, dB);
            dB = fmaf(xv.z, (float)qb.z, dB);
            dB = fmaf(xv.w, (float)qb.w, dB);
            accB = fmaf(sB, dB, accB);
        }

        // Warp reductions
        #pragma unroll
        for (int off = 16; off > 0; off >>= 1) {
            accA += __shfl_xor_sync(0xffffffffu, accA, off);
            accB += __shfl_xor_sync(0xffffffffu, accB, off);
        }

        if (lane == 0) {
            out[rowA] = accA + __ldg(&bias[rowA]);
            out[rowB] = accB + __ldg(&bias[rowB]);
        }

        t = nt;
    }

    // Self-reset for the next graph replay: last CTA to finish zeroes state.
    __syncthreads();
    if (threadIdx.x == 0) {
        __threadfence();
        if (atomicAdd(&g_done, 1u) == GRID - 1u) {
            g_ctr  = 0u;
            g_done = 0u;
            __threadfence();
        }
    }
}

extern "C" void kernel_launch(void* const* d_in, const int* in_sizes, int n_in,
                              void* d_out, int out_size)
{
    const float* x      = (const float*)d_in[0];
    const int*   q      = (const int*)d_in[1];
    const float* scales = (const float*)d_in[2];
    const float* bias   = (const float*)d_in[3];
    float*       out    = (float*)d_out;

    ggml_q8_gemv<<<GRID, THREADS>>>(x, q, scales, bias, out);
}

// round 17
// speedup vs baseline: 1.2078x; 1.2078x over previous
#include <cuda_runtime.h>
#include <cuda_bf16.h>

// GGMLLinear: out[o] = sum_k x[k] * scales[o, k/32] * q[o,k] + bias[o]
// x: [1, 4096] f32, q: [14336, 4096] int32 (int8-range), scales: [14336, 128] f32,
// bias: [14336] f32, out: [1, 14336] f32.
//
// Memory-bound GEMV (235MB q stream). R16 = R8 (the proven optimum across
// 15 rounds: 128 thr, 4 warps x 2 rows, 64 regs, smem x, unroll 4,
// strided-scale shuffle, grid=1792, static partitioning) with ONE isolated
// change: __ldcs on the q stream (evict-first L2 policy for the zero-reuse
// 235MB stream, protecting L2 residency of the x lines that 1792 CTAs
// re-read while staging). Everything else bit-identical to R8.

#define IN_DIM 4096
#define OUT_DIM 14336
#define NB (IN_DIM / 32)          // 128 scale blocks per row
#define ROWS_PER_CTA 8            // 4 warps x 2 rows
#define THREADS 128

__global__ __launch_bounds__(THREADS, 8)
void ggml_q8_gemv(const float* __restrict__ x,
                  const int* __restrict__ q,
                  const float* __restrict__ scales,
                  const float* __restrict__ bias,
                  float* __restrict__ out)
{
    __shared__ float xs[IN_DIM];

    // Stage x (16KB) into shared. 1024 float4 / 128 threads = 8 each.
    {
        const float4* x4 = reinterpret_cast<const float4*>(x);
        float4* xs4 = reinterpret_cast<float4*>(xs);
        #pragma unroll
        for (int i = threadIdx.x; i < IN_DIM / 4; i += THREADS)
            xs4[i] = x4[i];
    }
    __syncthreads();

    const int warp = threadIdx.x >> 5;
    const int lane = threadIdx.x & 31;
    const int rowA = blockIdx.x * ROWS_PER_CTA + warp * 2;   // grid sized exactly
    const int rowB = rowA + 1;

    const int4*   qrowA = reinterpret_cast<const int4*>(q + (size_t)rowA * IN_DIM);
    const int4*   qrowB = reinterpret_cast<const int4*>(q + (size_t)rowB * IN_DIM);
    const float4* xs4   = reinterpret_cast<const float4*>(xs);

    // Preload all 128 scales per row, strided: lane L holds scale[L + 32*r].
    // Scale for iter it, lane L: scale[4*it + (L>>3)]
    //   = reg (it>>3) of lane ((it&7)*4 + (L>>3)).
    const float* srowA = scales + (size_t)rowA * NB;
    const float* srowB = scales + (size_t)rowB * NB;
    const float a0 = __ldg(&srowA[lane]);
    const float a1 = __ldg(&srowA[lane + 32]);
    const float a2 = __ldg(&srowA[lane + 64]);
    const float a3 = __ldg(&srowA[lane + 96]);
    const float b0 = __ldg(&srowB[lane]);
    const float b1 = __ldg(&srowB[lane + 32]);
    const float b2 = __ldg(&srowB[lane + 64]);
    const float b3 = __ldg(&srowB[lane + 96]);
    const int csel = lane >> 3;

    float accA = 0.0f;
    float accB = 0.0f;

    // 1024 int4 per row / 32 lanes = 32 steps. idx4 = it*32 + lane.
    #pragma unroll 4
    for (int it = 0; it < 32; ++it) {
        const int idx4 = it * 32 + lane;
        const int4   qa = __ldcs(&qrowA[idx4]);   // evict-first: zero-reuse stream
        const int4   qb = __ldcs(&qrowB[idx4]);
        const float4 xv = xs4[idx4];
        const int    src = ((it & 7) << 2) + csel;
        const float  sva = (it < 8) ? a0 : (it < 16) ? a1 : (it < 24) ? a2 : a3;
        const float  svb = (it < 8) ? b0 : (it < 16) ? b1 : (it < 24) ? b2 : b3;
        const float  sA = __shfl_sync(0xffffffffu, sva, src);
        const float  sB = __shfl_sync(0xffffffffu, svb, src);

        float dA = xv.x * (float)qa.x;
        dA = fmaf(xv.y, (float)qa.y, dA);
        dA = fmaf(xv.z, (float)qa.z, dA);
        dA = fmaf(xv.w, (float)qa.w, dA);
        accA = fmaf(sA, dA, accA);

        float dB = xv.x * (float)qb.x;
        dB = fmaf(xv.y, (float)qb.y, dB);
        dB = fmaf(xv.z, (float)qb.z, dB);
        dB = fmaf(xv.w, (float)qb.w, dB);
        accB = fmaf(sB, dB, accB);
    }

    // Warp reductions
    #pragma unroll
    for (int off = 16; off > 0; off >>= 1) {
        accA += __shfl_xor_sync(0xffffffffu, accA, off);
        accB += __shfl_xor_sync(0xffffffffu, accB, off);
    }

    if (lane == 0) {
        out[rowA] = accA + __ldg(&bias[rowA]);
        out[rowB] = accB + __ldg(&bias[rowB]);
    }
}

extern "C" void kernel_launch(void* const* d_in, const int* in_sizes, int n_in,
                              void* d_out, int out_size)
{
    const float* x      = (const float*)d_in[0];
    const int*   q      = (const int*)d_in[1];
    const float* scales = (const float*)d_in[2];
    const float* bias   = (const float*)d_in[3];
    float*       out    = (float*)d_out;

    const int grid = OUT_DIM / ROWS_PER_CTA;   // 1792
    ggml_q8_gemv<<<grid, THREADS>>>(x, q, scales, bias, out);
}